// round 14
// baseline (speedup 1.0000x reference)
#include <cuda_runtime.h>
#include <cuda_bf16.h>
#include <math.h>

#define BB 4
#define NN 10000
#define DD 256
#define EE 160000
#define SS 2
#define NPASS 6
#define HID 80
#define OUTD 10
#define MROWS (BB * NN)   // 40000
#define AW_PITCH 132
#define GRID_M ((MROWS + 127) / 128)   // 313

// ---------------- device scratch ----------------
__device__ float g_h  [MROWS * DD];
__device__ float g_inc[MROWS * DD];
__device__ float g_gi [MROWS * 3 * DD];
__device__ float g_gh [MROWS * 3 * DD];
__device__ float g_s  [BB * DD];
__device__ float g_u  [SS][MROWS * DD];
__device__ float g_deg[SS][MROWS];
__device__ int   g_off[SS][MROWS];
__device__ int   g_cur[SS][MROWS];
__device__ int   g_csr[SS][BB * EE];
__device__ __align__(16) unsigned g_hhi[MROWS * 128];
__device__ __align__(16) unsigned g_hlo[MROWS * 128];
__device__ __align__(16) unsigned g_Thi[SS][MROWS * 128];
__device__ __align__(16) unsigned g_Tlo[SS][MROWS * 128];
__device__ __align__(16) unsigned g_ewt[2][SS][16][2][2048];
__device__ __align__(16) unsigned g_gwt[2][3][16][2][2048];

// ---------------- PTX helpers ----------------
__device__ __forceinline__ unsigned smem_u32(const void* p) {
    unsigned a;
    asm("{ .reg .u64 t; cvta.to.shared.u64 t, %1; cvt.u32.u64 %0, t; }" : "=r"(a) : "l"(p));
    return a;
}
#define MB_INIT(mb, c) asm volatile("mbarrier.init.shared.b64 [%0], %1;" :: "r"(mb), "r"(c) : "memory")
#define MB_EXPECT(mb, n) asm volatile("mbarrier.arrive.expect_tx.shared.b64 _, [%0], %1;" :: "r"(mb), "r"(n) : "memory")
#define MB_ARRIVE(mb) asm volatile("mbarrier.arrive.shared.b64 _, [%0];" :: "r"(mb) : "memory")
#define MB_WAIT(mb, ph) do { \
    unsigned _m = (mb), _p = (ph), _d; \
    asm volatile("{\n\t.reg .pred p;\n\t" \
        "mbarrier.try_wait.parity.acquire.cta.shared::cta.b64 p, [%1], %2;\n\t" \
        "selp.b32 %0, 1, 0, p;\n\t}" : "=r"(_d) : "r"(_m), "r"(_p) : "memory"); \
    if (!_d) { \
        asm volatile("{\n\t.reg .pred P1;\n\tWL_%=:\n\t" \
            "mbarrier.try_wait.parity.acquire.cta.shared::cta.b64 P1, [%0], %1, 0x989680;\n\t" \
            "@P1 bra.uni WD_%=;\n\tbra.uni WL_%=;\n\tWD_%=:\n\t}" :: "r"(_m), "r"(_p) : "memory"); \
    } \
} while (0)
__device__ __forceinline__ void bulk_g2s(unsigned dst, const void* src, unsigned bytes, unsigned mbar) {
    asm volatile("cp.async.bulk.shared::cluster.global.mbarrier::complete_tx::bytes [%0], [%1], %2, [%3];"
        :: "r"(dst), "l"(src), "r"(bytes), "r"(mbar) : "memory");
}
#define CP16(dst, src) asm volatile("cp.async.cg.shared.global [%0], [%1], 16;" :: "r"(dst), "l"(src) : "memory")
#define CP_COMMIT() asm volatile("cp.async.commit_group;" ::: "memory")
#define CP_WAIT(n)  asm volatile("cp.async.wait_group %0;" :: "n"(n) : "memory")
#define LDSM4(r0, r1, r2, r3, a) \
    asm volatile("ldmatrix.sync.aligned.m8n8.x4.shared.b16 {%0,%1,%2,%3}, [%4];" \
        : "=r"(r0), "=r"(r1), "=r"(r2), "=r"(r3) : "r"(a))
__device__ __forceinline__ void mma16816(float c[4], unsigned a0, unsigned a1, unsigned a2, unsigned a3,
                                         unsigned b0, unsigned b1) {
    asm volatile("mma.sync.aligned.m16n8k16.row.col.f32.bf16.bf16.f32 "
        "{%0,%1,%2,%3}, {%4,%5,%6,%7}, {%8,%9}, {%0,%1,%2,%3};"
        : "+f"(c[0]), "+f"(c[1]), "+f"(c[2]), "+f"(c[3])
        : "r"(a0), "r"(a1), "r"(a2), "r"(a3), "r"(b0), "r"(b1));
}
__device__ __forceinline__ unsigned pack2(float a, float b) {
    __nv_bfloat162 t = __floats2bfloat162_rn(a, b);
    return *(unsigned*)&t;
}

// ---------------- smem layout (bytes): M=128 GEMM CTAs ----------------
#define OFF_ALO2 67584           /* 128*132*4 */
#define OFF_W2   135168          /* 2 x 16KB */
#define OFF_BAR2 167936
#define TSMEM2   168000

// ---------------- setup kernels ----------------
__global__ void zero4(float4* __restrict__ dst, int n4) {
    int i = blockIdx.x * 256 + threadIdx.x;
    if (i < n4) dst[i] = make_float4(0.f, 0.f, 0.f, 0.f);
}
__global__ void split_init(const float* __restrict__ nodes) {
    size_t i2 = (size_t)blockIdx.x * 256 + threadIdx.x;
    float2 v = ((const float2*)nodes)[i2];
    ((float2*)g_h)[i2] = v;
    float h0 = __bfloat162float(__float2bfloat16(v.x));
    float h1 = __bfloat162float(__float2bfloat16(v.y));
    g_hhi[i2] = pack2(h0, h1);
    g_hlo[i2] = pack2(v.x - h0, v.y - h1);
}
__global__ void prep_weights(const float* __restrict__ w1, const float* __restrict__ w2,
                             const float* __restrict__ wih, const float* __restrict__ whh) {
    int idx = blockIdx.x * 256 + threadIdx.x;
    if (idx < 2 * SS * 256 * 256) {
        int k  = idx & 255;
        int n  = (idx >> 8) & 255;
        int si = (idx >> 16) & 1;
        int st = idx >> 17;
        float w = (st == 0 ? w1 : w2)[si * 65536 + n * 256 + k];
        __nv_bfloat16 hi = __float2bfloat16(w);
        __nv_bfloat16 lo = __float2bfloat16(w - __bfloat162float(hi));
        int ch = k >> 4;
        int word = n * 8 + (((((k >> 3) & 1)) ^ ((n >> 2) & 1)) << 2) + ((k & 7) >> 1);
        ((__nv_bfloat16*)&g_ewt[st][si][ch][0][word])[k & 1] = hi;
        ((__nv_bfloat16*)&g_ewt[st][si][ch][1][word])[k & 1] = lo;
    }
    if (idx < 2 * 768 * 256) {
        int k = idx & 255;
        int e = (idx >> 8) % 768;
        int wh = idx / (768 * 256);
        float w = (wh == 0 ? wih : whh)[e * 256 + k];
        __nv_bfloat16 hi = __float2bfloat16(w);
        __nv_bfloat16 lo = __float2bfloat16(w - __bfloat162float(hi));
        int ny = e >> 8, n = e & 255;
        int ch = k >> 4;
        int word = n * 8 + (((((k >> 3) & 1)) ^ ((n >> 2) & 1)) << 2) + ((k & 7) >> 1);
        ((__nv_bfloat16*)&g_gwt[wh][ny][ch][0][word])[k & 1] = hi;
        ((__nv_bfloat16*)&g_gwt[wh][ny][ch][1][word])[k & 1] = lo;
    }
}
__global__ void deg_count(const int* __restrict__ edges) {
    int e = blockIdx.x * 256 + threadIdx.x;
    int b = blockIdx.y, si = blockIdx.z;
    int dst = ((const int2*)edges)[((size_t)(b * SS + si)) * EE + e].x;
    atomicAdd(&g_deg[si][b * NN + dst], 1.0f);
}
__global__ void scan_deg() {
    int si = blockIdx.x, t = threadIdx.x;
    __shared__ int ps[1024];
    int base = t * 40;
    int s = 0;
    for (int i = 0; i < 40; ++i) {
        int idx = base + i;
        if (idx < MROWS) s += (int)g_deg[si][idx];
    }
    ps[t] = s;
    __syncthreads();
    for (int off = 1; off < 1024; off <<= 1) {
        int v = (t >= off) ? ps[t - off] : 0;
        __syncthreads();
        ps[t] += v;
        __syncthreads();
    }
    int run = ps[t] - s;
    for (int i = 0; i < 40; ++i) {
        int idx = base + i;
        if (idx < MROWS) {
            g_off[si][idx] = run;
            g_cur[si][idx] = run;
            run += (int)g_deg[si][idx];
        }
    }
}
__global__ void csr_fill(const int* __restrict__ edges) {
    int e = blockIdx.x * 256 + threadIdx.x;
    int b = blockIdx.y, si = blockIdx.z;
    int2 de = ((const int2*)edges)[((size_t)(b * SS + si)) * EE + e];
    int pos = atomicAdd(&g_cur[si][b * NN + de.x], 1);
    g_csr[si][pos] = b * NN + de.y;
}

// ---------------- HMMA for one 16-k chunk (per-warp) ----------------
__device__ __forceinline__ void hmma_chunk16(
    unsigned aHi, unsigned aLo, unsigned wB, float acc[2][8][4])
{
    unsigned ah[2][4], al[2][4];
#pragma unroll
    for (int mt = 0; mt < 2; ++mt) {
        unsigned off = mt * (16 * AW_PITCH * 4);
        LDSM4(ah[mt][0], ah[mt][1], ah[mt][2], ah[mt][3], aHi + off);
        LDSM4(al[mt][0], al[mt][1], al[mt][2], al[mt][3], aLo + off);
    }
#pragma unroll
    for (int p = 0; p < 4; ++p) {
        unsigned bh[4], bl[4];
        LDSM4(bh[0], bh[1], bh[2], bh[3], wB + p * 512);
        LDSM4(bl[0], bl[1], bl[2], bl[3], wB + p * 512 + 8192);
#pragma unroll
        for (int mt = 0; mt < 2; ++mt) {
            mma16816(acc[mt][2*p],   ah[mt][0], ah[mt][1], ah[mt][2], ah[mt][3], bh[0], bh[1]);
            mma16816(acc[mt][2*p],   al[mt][0], al[mt][1], al[mt][2], al[mt][3], bh[0], bh[1]);
            mma16816(acc[mt][2*p],   ah[mt][0], ah[mt][1], ah[mt][2], ah[mt][3], bl[0], bl[1]);
            mma16816(acc[mt][2*p+1], ah[mt][0], ah[mt][1], ah[mt][2], ah[mt][3], bh[2], bh[3]);
            mma16816(acc[mt][2*p+1], al[mt][0], al[mt][1], al[mt][2], al[mt][3], bh[2], bh[3]);
            mma16816(acc[mt][2*p+1], ah[mt][0], ah[mt][1], ah[mt][2], ah[mt][3], bl[2], bl[3]);
        }
    }
}
__device__ __forceinline__ unsigned b_thread_off(int wn, int lane) {
    return ((unsigned)(wn * 512 + ((lane >> 4) & 1) * 64 + (lane & 7) * 8) << 2)
         + ((((lane >> 3) ^ (lane >> 2)) & 1) << 4);
}
// 512-thread loaders for 128 rows (row clamped to MROWS-1)
__device__ __forceinline__ void load_split_rows128(
    unsigned* Ahw, unsigned* Alw, const float* __restrict__ src, int row0, int tid)
{
    int r = tid >> 2, q = tid & 3;
    int rr = row0 + r; if (rr >= MROWS) rr = MROWS - 1;
    const float4* sp = (const float4*)(src + (size_t)rr * DD) + q * 16;
    unsigned* dh = Ahw + r * AW_PITCH + q * 32;
    unsigned* dl = Alw + r * AW_PITCH + q * 32;
#pragma unroll
    for (int i = 0; i < 16; ++i) {
        float4 v = sp[i];
        float h0 = __bfloat162float(__float2bfloat16(v.x));
        float h1 = __bfloat162float(__float2bfloat16(v.y));
        float h2 = __bfloat162float(__float2bfloat16(v.z));
        float h3 = __bfloat162float(__float2bfloat16(v.w));
        dh[2 * i]     = pack2(h0, h1);
        dh[2 * i + 1] = pack2(h2, h3);
        dl[2 * i]     = pack2(v.x - h0, v.y - h1);
        dl[2 * i + 1] = pack2(v.z - h2, v.w - h3);
    }
}
__device__ __forceinline__ void cp_split_rows128(
    unsigned sb, const unsigned* __restrict__ hi, const unsigned* __restrict__ lo,
    int row0, int tid)
{
    int r = tid >> 2, q = tid & 3;
    int rr = row0 + r; if (rr >= MROWS) rr = MROWS - 1;
    size_t grow = (size_t)rr * 128 + q * 32;
    unsigned dh = sb + (r * AW_PITCH + q * 32) * 4;
    unsigned dl = dh + OFF_ALO2;
#pragma unroll
    for (int i = 0; i < 8; ++i) {
        CP16(dh + 16 * i, hi + grow + 4 * i);
        CP16(dl + 16 * i, lo + grow + 4 * i);
    }
    CP_COMMIT();
}

// ---------------- U GEMM: U_si = leaky(h * W1_si^T + b1_si), 128 rows/CTA -------
__global__ void __launch_bounds__(512, 1) u_tc(const float* __restrict__ eb1) {
    extern __shared__ char smem[];
    unsigned sb = smem_u32(smem);
    unsigned bar = sb + OFF_BAR2;
    int tid = threadIdx.x, lane = tid & 31, wid = tid >> 5;
    int wm = wid >> 2, wn = wid & 3;
    int row0 = blockIdx.x * 128, si = blockIdx.y;

    unsigned aHi0 = sb + (wm * 32 + (lane & 15)) * (AW_PITCH * 4) + (lane >> 4) * 16;
    unsigned wOff = b_thread_off(wn, lane);

    if (tid == 0) {
        MB_INIT(bar + 0, 1);   MB_INIT(bar + 8, 1);
        MB_INIT(bar + 16, 16); MB_INIT(bar + 24, 16);
    }
    __syncthreads();
    if (tid == 0) {
#pragma unroll
        for (int g = 0; g < 2; ++g) {
            MB_EXPECT(bar + 8 * g, 16384);
            bulk_g2s(sb + OFF_W2 + g * 16384, &g_ewt[0][si][g][0][0], 16384, bar + 8 * g);
        }
    }
    cp_split_rows128(sb, g_hhi, g_hlo, row0, tid);
    CP_WAIT(0);
    __syncthreads();

    float acc[2][8][4];
#pragma unroll
    for (int mt = 0; mt < 2; ++mt)
#pragma unroll
        for (int ng = 0; ng < 8; ++ng)
#pragma unroll
            for (int i = 0; i < 4; ++i) acc[mt][ng][i] = 0.f;

    int fph[2] = {0, 0}, eph[2] = {0, 0};
    for (int kc = 0; kc < 16; ++kc) {
        int buf = kc & 1;
        MB_WAIT(bar + 8 * buf, fph[buf]); fph[buf] ^= 1;
        hmma_chunk16(aHi0 + kc * 32, aHi0 + kc * 32 + OFF_ALO2,
                     sb + OFF_W2 + buf * 16384 + wOff, acc);
        if (lane == 0) MB_ARRIVE(bar + 16 + 8 * buf);
        if (tid == 0 && kc < 14) {
            MB_WAIT(bar + 16 + 8 * buf, eph[buf]); eph[buf] ^= 1;
            MB_EXPECT(bar + 8 * buf, 16384);
            bulk_g2s(sb + OFF_W2 + buf * 16384, &g_ewt[0][si][kc + 2][0][0], 16384, bar + 8 * buf);
        }
    }

    const float* b1s = eb1 + si * DD;
    float* up = g_u[si];
#pragma unroll
    for (int mt = 0; mt < 2; ++mt) {
#pragma unroll
        for (int half = 0; half < 2; ++half) {
            int row = row0 + wm * 32 + mt * 16 + (lane >> 2) + half * 8;
            if (row < MROWS) {
                float* cp = up + (size_t)row * DD;
#pragma unroll
                for (int nf = 0; nf < 8; ++nf) {
                    int ncol = wn * 64 + nf * 8 + (lane & 3) * 2;
                    float2 bv = *(const float2*)(b1s + ncol);
                    float v0 = acc[mt][nf][half * 2 + 0] + bv.x;
                    float v1 = acc[mt][nf][half * 2 + 1] + bv.y;
                    v0 = v0 > 0.f ? v0 : 0.01f * v0;
                    v1 = v1 > 0.f ? v1 : 0.01f * v1;
                    *(float2*)(cp + ncol) = make_float2(v0, v1);
                }
            }
        }
    }
}

// ---------------- gather-sum (unrolled x2): T_si[row] = sum U_si[src] ----------
__global__ void __launch_bounds__(256) gather_sum() {
    int lane = threadIdx.x & 31;
    int w = blockIdx.x * 8 + (threadIdx.x >> 5);
    int si = w / MROWS, row = w - si * MROWS;
    int beg = g_off[si][row];
    int cnt = (int)g_deg[si][row];
    const float* ub = g_u[si];
    const int* cs = g_csr[si] + beg;
    float4 a0 = make_float4(0.f, 0.f, 0.f, 0.f);
    float4 a1 = make_float4(0.f, 0.f, 0.f, 0.f);
    int i = 0;
    for (; i + 2 <= cnt; i += 2) {
        const float4* p0 = (const float4*)(ub + (size_t)cs[i] * DD);
        const float4* p1 = (const float4*)(ub + (size_t)cs[i + 1] * DD);
        float4 u0 = p0[lane], u1 = p0[lane + 32];
        float4 v0 = p1[lane], v1 = p1[lane + 32];
        a0.x += u0.x + v0.x; a0.y += u0.y + v0.y; a0.z += u0.z + v0.z; a0.w += u0.w + v0.w;
        a1.x += u1.x + v1.x; a1.y += u1.y + v1.y; a1.z += u1.z + v1.z; a1.w += u1.w + v1.w;
    }
    if (i < cnt) {
        const float4* p0 = (const float4*)(ub + (size_t)cs[i] * DD);
        float4 u0 = p0[lane], u1 = p0[lane + 32];
        a0.x += u0.x; a0.y += u0.y; a0.z += u0.z; a0.w += u0.w;
        a1.x += u1.x; a1.y += u1.y; a1.z += u1.z; a1.w += u1.w;
    }
    size_t rb = (size_t)row * 128;
    unsigned* th = g_Thi[si];
    unsigned* tl = g_Tlo[si];
    float h0, h1;
    h0 = __bfloat162float(__float2bfloat16(a0.x)); h1 = __bfloat162float(__float2bfloat16(a0.y));
    th[rb + lane * 2 + 0] = pack2(h0, h1);
    tl[rb + lane * 2 + 0] = pack2(a0.x - h0, a0.y - h1);
    h0 = __bfloat162float(__float2bfloat16(a0.z)); h1 = __bfloat162float(__float2bfloat16(a0.w));
    th[rb + lane * 2 + 1] = pack2(h0, h1);
    tl[rb + lane * 2 + 1] = pack2(a0.z - h0, a0.w - h1);
    h0 = __bfloat162float(__float2bfloat16(a1.x)); h1 = __bfloat162float(__float2bfloat16(a1.y));
    th[rb + 64 + lane * 2 + 0] = pack2(h0, h1);
    tl[rb + 64 + lane * 2 + 0] = pack2(a1.x - h0, a1.y - h1);
    h0 = __bfloat162float(__float2bfloat16(a1.z)); h1 = __bfloat162float(__float2bfloat16(a1.w));
    th[rb + 64 + lane * 2 + 1] = pack2(h0, h1);
    tl[rb + 64 + lane * 2 + 1] = pack2(a1.z - h0, a1.w - h1);
}

// ---------------- inc GEMM: inc = T0*W2_0^T + T1*W2_1^T + deg*b2, 128 rows/CTA --
__global__ void __launch_bounds__(512, 1) inc_tc(const float* __restrict__ eb2) {
    extern __shared__ char smem[];
    unsigned sb = smem_u32(smem);
    unsigned bar = sb + OFF_BAR2;
    int tid = threadIdx.x, lane = tid & 31, wid = tid >> 5;
    int wm = wid >> 2, wn = wid & 3;
    int row0 = blockIdx.x * 128;

    unsigned aHi0 = sb + (wm * 32 + (lane & 15)) * (AW_PITCH * 4) + (lane >> 4) * 16;
    unsigned wOff = b_thread_off(wn, lane);

    if (tid == 0) {
        MB_INIT(bar + 0, 1);   MB_INIT(bar + 8, 1);
        MB_INIT(bar + 16, 16); MB_INIT(bar + 24, 16);
    }
    __syncthreads();
    if (tid == 0) {
#pragma unroll
        for (int g = 0; g < 2; ++g) {
            MB_EXPECT(bar + 8 * g, 16384);
            bulk_g2s(sb + OFF_W2 + g * 16384, &g_ewt[1][0][g][0][0], 16384, bar + 8 * g);
        }
    }
    cp_split_rows128(sb, g_Thi[0], g_Tlo[0], row0, tid);
    CP_WAIT(0);
    __syncthreads();

    float acc[2][8][4];
#pragma unroll
    for (int mt = 0; mt < 2; ++mt)
#pragma unroll
        for (int ng = 0; ng < 8; ++ng)
#pragma unroll
            for (int i = 0; i < 4; ++i) acc[mt][ng][i] = 0.f;

    int fph[2] = {0, 0}, eph[2] = {0, 0};
    for (int kc = 0; kc < 32; ++kc) {
        int buf = kc & 1;
        MB_WAIT(bar + 8 * buf, fph[buf]); fph[buf] ^= 1;
        if (kc == 16) {
            __syncthreads();
            cp_split_rows128(sb, g_Thi[1], g_Tlo[1], row0, tid);
            CP_WAIT(0);
            __syncthreads();
        }
        hmma_chunk16(aHi0 + (kc & 15) * 32, aHi0 + (kc & 15) * 32 + OFF_ALO2,
                     sb + OFF_W2 + buf * 16384 + wOff, acc);
        if (lane == 0) MB_ARRIVE(bar + 16 + 8 * buf);
        if (tid == 0 && kc < 30) {
            MB_WAIT(bar + 16 + 8 * buf, eph[buf]); eph[buf] ^= 1;
            int c1 = kc + 2, si2 = c1 >> 4, ch = c1 & 15;
            MB_EXPECT(bar + 8 * buf, 16384);
            bulk_g2s(sb + OFF_W2 + buf * 16384, &g_ewt[1][si2][ch][0][0], 16384, bar + 8 * buf);
        }
    }

    const float* b20 = eb2;
    const float* b21 = eb2 + DD;
#pragma unroll
    for (int mt = 0; mt < 2; ++mt) {
#pragma unroll
        for (int half = 0; half < 2; ++half) {
            int row = row0 + wm * 32 + mt * 16 + (lane >> 2) + half * 8;
            if (row < MROWS) {
                float d0 = g_deg[0][row];
                float d1 = g_deg[1][row];
                float* cp = g_inc + (size_t)row * DD;
#pragma unroll
                for (int nf = 0; nf < 8; ++nf) {
                    int ncol = wn * 64 + nf * 8 + (lane & 3) * 2;
                    float2 p0 = *(const float2*)(b20 + ncol);
                    float2 p1 = *(const float2*)(b21 + ncol);
                    float2 v;
                    v.x = acc[mt][nf][half * 2 + 0] + d0 * p0.x + d1 * p1.x;
                    v.y = acc[mt][nf][half * 2 + 1] + d0 * p0.y + d1 * p1.y;
                    *(float2*)(cp + ncol) = v;
                }
            }
        }
    }
}

// ---------------- GRU GEMM: 128 rows/CTA, which = blockIdx.z ----------------
__global__ void __launch_bounds__(512, 1) gru_tc(
    const float* __restrict__ b_ih, const float* __restrict__ b_hh)
{
    extern __shared__ char smem[];
    unsigned sb = smem_u32(smem);
    unsigned* Ahw = (unsigned*)smem;
    unsigned* Alw = Ahw + OFF_ALO2 / 4;
    unsigned bar = sb + OFF_BAR2;

    int tid = threadIdx.x, lane = tid & 31, wid = tid >> 5;
    int wm = wid >> 2, wn = wid & 3;
    int row0 = blockIdx.x * 128;
    int ny = blockIdx.y, col0 = ny * 256;
    int which = blockIdx.z;

    unsigned aHi0 = sb + (wm * 32 + (lane & 15)) * (AW_PITCH * 4) + (lane >> 4) * 16;
    unsigned wOff = b_thread_off(wn, lane);

    if (tid == 0) {
        MB_INIT(bar + 0, 1);   MB_INIT(bar + 8, 1);
        MB_INIT(bar + 16, 16); MB_INIT(bar + 24, 16);
    }
    __syncthreads();
    if (tid == 0) {
#pragma unroll
        for (int g = 0; g < 2; ++g) {
            MB_EXPECT(bar + 8 * g, 16384);
            bulk_g2s(sb + OFF_W2 + g * 16384, &g_gwt[which][ny][g][0][0], 16384, bar + 8 * g);
        }
    }
    if (which == 1) {
        cp_split_rows128(sb, g_hhi, g_hlo, row0, tid);
        CP_WAIT(0);
    } else {
        load_split_rows128(Ahw, Alw, g_inc, row0, tid);
    }
    __syncthreads();

    float acc[2][8][4];
#pragma unroll
    for (int mt = 0; mt < 2; ++mt)
#pragma unroll
        for (int ng = 0; ng < 8; ++ng)
#pragma unroll
            for (int i = 0; i < 4; ++i) acc[mt][ng][i] = 0.f;

    int fph[2] = {0, 0}, eph[2] = {0, 0};
    for (int kc = 0; kc < 16; ++kc) {
        int buf = kc & 1;
        MB_WAIT(bar + 8 * buf, fph[buf]); fph[buf] ^= 1;
        hmma_chunk16(aHi0 + kc * 32, aHi0 + kc * 32 + OFF_ALO2,
                     sb + OFF_W2 + buf * 16384 + wOff, acc);
        if (lane == 0) MB_ARRIVE(bar + 16 + 8 * buf);
        if (tid == 0 && kc < 14) {
            MB_WAIT(bar + 16 + 8 * buf, eph[buf]); eph[buf] ^= 1;
            MB_EXPECT(bar + 8 * buf, 16384);
            bulk_g2s(sb + OFF_W2 + buf * 16384, &g_gwt[which][ny][kc + 2][0][0], 16384, bar + 8 * buf);
        }
    }

    const float* bias = (which == 0 ? b_ih : b_hh);
    float* C = (which == 0 ? g_gi : g_gh);
#pragma unroll
    for (int mt = 0; mt < 2; ++mt) {
#pragma unroll
        for (int half = 0; half < 2; ++half) {
            int row = row0 + wm * 32 + mt * 16 + (lane >> 2) + half * 8;
            if (row < MROWS) {
                float* cp = C + (size_t)row * 768 + col0;
#pragma unroll
                for (int nf = 0; nf < 8; ++nf) {
                    int ncol = wn * 64 + nf * 8 + (lane & 3) * 2;
                    float2 bv = *(const float2*)(bias + col0 + ncol);
                    float2 v;
                    v.x = acc[mt][nf][half * 2 + 0] + bv.x;
                    v.y = acc[mt][nf][half * 2 + 1] + bv.y;
                    *(float2*)(cp + ncol) = v;
                }
            }
        }
    }
}

// ---------------- GRU gates + h split refresh ----------------
__global__ void gru_gate2(const float* __restrict__ gi, const float* __restrict__ gh) {
    size_t i2 = (size_t)blockIdx.x * 256 + threadIdx.x;
    size_t row = i2 >> 7;
    int d = (int)(i2 & 127) * 2;
    const float* gir = gi + row * 768;
    const float* ghr = gh + row * 768;
    float2 ir = *(const float2*)(gir + d);
    float2 iz = *(const float2*)(gir + 256 + d);
    float2 in2 = *(const float2*)(gir + 512 + d);
    float2 hr = *(const float2*)(ghr + d);
    float2 hz = *(const float2*)(ghr + 256 + d);
    float2 hn = *(const float2*)(ghr + 512 + d);
    float2 hv = ((const float2*)g_h)[i2];
    float r0 = 1.f / (1.f + expf(-(ir.x + hr.x)));
    float r1 = 1.f / (1.f + expf(-(ir.y + hr.y)));
    float z0 = 1.f / (1.f + expf(-(iz.x + hz.x)));
    float z1 = 1.f / (1.f + expf(-(iz.y + hz.y)));
    float n0 = tanhf(in2.x + r0 * hn.x);
    float n1 = tanhf(in2.y + r1 * hn.y);
    float h0 = (1.f - z0) * n0 + z0 * hv.x;
    float h1 = (1.f - z1) * n1 + z1 * hv.y;
    ((float2*)g_h)[i2] = make_float2(h0, h1);
    float e0 = __bfloat162float(__float2bfloat16(h0));
    float e1 = __bfloat162float(__float2bfloat16(h1));
    g_hhi[i2] = pack2(e0, e1);
    g_hlo[i2] = pack2(h0 - e0, h1 - e1);
}

// ---------------- node sum + head ----------------
__global__ void node_sum() {
    int b = blockIdx.x, chunk = blockIdx.y;
    int d = threadIdx.x;
    const float* base = g_h + ((size_t)b * NN + chunk * 250) * DD + d;
    float acc = 0.f;
    for (int n = 0; n < 250; ++n) acc += base[(size_t)n * DD];
    atomicAdd(&g_s[b * DD + d], acc);
}

__global__ void head_kernel(const float* __restrict__ ptype,
                            const float* __restrict__ fc1w, const float* __restrict__ fc1b,
                            const float* __restrict__ fc2w, const float* __restrict__ fc2b,
                            const float* __restrict__ fc3w, const float* __restrict__ fc3b,
                            float* __restrict__ out)
{
    int b = blockIdx.x, tid = threadIdx.x;
    __shared__ float xs[257];
    __shared__ float red[256];
    __shared__ float a1[HID], a2[HID];

    float sv = g_s[b * DD + tid];
    float l = logf(sv);
    if (isnan(l)) l = 0.f;
    l = fmaxf(l, 0.f);
    float fm = isinf(l) ? -INFINITY : l;
    red[tid] = fm;
    __syncthreads();
    for (int off = 128; off > 0; off >>= 1) {
        if (tid < off) red[tid] = fmaxf(red[tid], red[tid + off]);
        __syncthreads();
    }
    float fmax = red[0];
    if (isinf(l)) l = fmax;
    xs[tid] = l;
    if (tid == 0) xs[256] = ptype[b];
    __syncthreads();

    if (tid < HID) {
        float acc = fc1b[tid];
        for (int k = 0; k < 257; ++k) acc += fc1w[tid * 257 + k] * xs[k];
        a1[tid] = acc > 0.f ? acc : 0.01f * acc;
    }
    __syncthreads();
    if (tid < HID) {
        float acc = fc2b[tid];
        for (int k = 0; k < HID; ++k) acc += fc2w[tid * HID + k] * a1[k];
        a2[tid] = acc > 0.f ? acc : 0.01f * acc;
    }
    __syncthreads();
    if (tid < OUTD) {
        float acc = fc3b[tid];
        for (int k = 0; k < HID; ++k) acc += fc3w[tid * HID + k] * a2[k];
        out[b * OUTD + tid] = acc;
    }
}

// ---------------- launch ----------------
extern "C" void kernel_launch(void* const* d_in, const int* in_sizes, int n_in,
                              void* d_out, int out_size) {
    const float* nodes = (const float*)d_in[0];
    const int*   edges = (const int*)  d_in[1];
    const float* ptype = (const float*)d_in[2];
    const float* w_ih  = (const float*)d_in[3];
    const float* w_hh  = (const float*)d_in[4];
    const float* b_ih  = (const float*)d_in[5];
    const float* b_hh  = (const float*)d_in[6];
    const float* ew1   = (const float*)d_in[7];
    const float* eb1   = (const float*)d_in[8];
    const float* ew2   = (const float*)d_in[9];
    const float* eb2   = (const float*)d_in[10];
    const float* fc1w  = (const float*)d_in[11];
    const float* fc1b  = (const float*)d_in[12];
    const float* fc2w  = (const float*)d_in[13];
    const float* fc2b  = (const float*)d_in[14];
    const float* fc3w  = (const float*)d_in[15];
    const float* fc3b  = (const float*)d_in[16];
    float* out = (float*)d_out;

    float *p_gi, *p_gh, *p_s, *p_deg;
    cudaGetSymbolAddress((void**)&p_gi,  g_gi);
    cudaGetSymbolAddress((void**)&p_gh,  g_gh);
    cudaGetSymbolAddress((void**)&p_s,   g_s);
    cudaGetSymbolAddress((void**)&p_deg, g_deg);

    cudaFuncSetAttribute(u_tc,   cudaFuncAttributeMaxDynamicSharedMemorySize, TSMEM2);
    cudaFuncSetAttribute(inc_tc, cudaFuncAttributeMaxDynamicSharedMemorySize, TSMEM2);
    cudaFuncSetAttribute(gru_tc, cudaFuncAttributeMaxDynamicSharedMemorySize, TSMEM2);

    split_init<<<MROWS * 128 / 256, 256>>>(nodes);
    prep_weights<<<1536, 256>>>(ew1, ew2, w_ih, w_hh);
    zero4<<<(SS * MROWS / 4 + 255) / 256, 256>>>((float4*)p_deg, SS * MROWS / 4);
    deg_count<<<dim3(EE / 256, BB, SS), 256>>>(edges);
    scan_deg<<<SS, 1024>>>();
    csr_fill<<<dim3(EE / 256, BB, SS), 256>>>(edges);

    for (int j = 0; j < NPASS; ++j) {
        u_tc<<<dim3(GRID_M, SS), 512, TSMEM2>>>(eb1);
        gather_sum<<<SS * MROWS / 8, 256>>>();
        inc_tc<<<GRID_M, 512, TSMEM2>>>(eb2);
        gru_tc<<<dim3(GRID_M, 3, 2), 512, TSMEM2>>>(b_ih, b_hh);
        gru_gate2<<<MROWS * 128 / 256, 256>>>(p_gi, p_gh);
    }

    zero4<<<1, 256>>>((float4*)p_s, BB * DD / 4);
    node_sum<<<dim3(BB, 40), 256>>>();
    head_kernel<<<BB, 256>>>(ptype, fc1w, fc1b, fc2w, fc2b, fc3w, fc3b, out);
}

// round 15
// speedup vs baseline: 1.1726x; 1.1726x over previous
#include <cuda_runtime.h>
#include <cuda_bf16.h>
#include <math.h>

#define BB 4
#define NN 10000
#define DD 256
#define EE 160000
#define SS 2
#define NPASS 6
#define HID 80
#define OUTD 10
#define MROWS (BB * NN)   // 40000
#define AW_PITCH 132

// ---------------- device scratch ----------------
__device__ float g_h  [MROWS * DD];
__device__ float g_inc[MROWS * DD];
__device__ float g_gi [MROWS * 3 * DD];
__device__ float g_gh [MROWS * 3 * DD];
__device__ float g_s  [BB * DD];
__device__ float g_u  [SS][MROWS * DD];
__device__ float g_deg[SS][MROWS];
__device__ int   g_off[SS][MROWS];
__device__ int   g_cur[SS][MROWS];
__device__ int   g_csr[SS][BB * EE];
__device__ __align__(16) unsigned g_hhi[MROWS * 128];
__device__ __align__(16) unsigned g_hlo[MROWS * 128];
__device__ __align__(16) unsigned g_Thi[SS][MROWS * 128];
__device__ __align__(16) unsigned g_Tlo[SS][MROWS * 128];
__device__ __align__(16) unsigned g_ewt[2][SS][16][2][2048];
__device__ __align__(16) unsigned g_gwt[2][3][16][2][2048];

// ---------------- PTX helpers ----------------
__device__ __forceinline__ unsigned smem_u32(const void* p) {
    unsigned a;
    asm("{ .reg .u64 t; cvta.to.shared.u64 t, %1; cvt.u32.u64 %0, t; }" : "=r"(a) : "l"(p));
    return a;
}
#define MB_INIT(mb, c) asm volatile("mbarrier.init.shared.b64 [%0], %1;" :: "r"(mb), "r"(c) : "memory")
#define MB_EXPECT(mb, n) asm volatile("mbarrier.arrive.expect_tx.shared.b64 _, [%0], %1;" :: "r"(mb), "r"(n) : "memory")
#define MB_ARRIVE(mb) asm volatile("mbarrier.arrive.shared.b64 _, [%0];" :: "r"(mb) : "memory")
#define MB_WAIT(mb, ph) do { \
    unsigned _m = (mb), _p = (ph), _d; \
    asm volatile("{\n\t.reg .pred p;\n\t" \
        "mbarrier.try_wait.parity.acquire.cta.shared::cta.b64 p, [%1], %2;\n\t" \
        "selp.b32 %0, 1, 0, p;\n\t}" : "=r"(_d) : "r"(_m), "r"(_p) : "memory"); \
    if (!_d) { \
        asm volatile("{\n\t.reg .pred P1;\n\tWL_%=:\n\t" \
            "mbarrier.try_wait.parity.acquire.cta.shared::cta.b64 P1, [%0], %1, 0x989680;\n\t" \
            "@P1 bra.uni WD_%=;\n\tbra.uni WL_%=;\n\tWD_%=:\n\t}" :: "r"(_m), "r"(_p) : "memory"); \
    } \
} while (0)
__device__ __forceinline__ void bulk_g2s(unsigned dst, const void* src, unsigned bytes, unsigned mbar) {
    asm volatile("cp.async.bulk.shared::cluster.global.mbarrier::complete_tx::bytes [%0], [%1], %2, [%3];"
        :: "r"(dst), "l"(src), "r"(bytes), "r"(mbar) : "memory");
}
#define CP16(dst, src) asm volatile("cp.async.cg.shared.global [%0], [%1], 16;" :: "r"(dst), "l"(src) : "memory")
#define CP_COMMIT() asm volatile("cp.async.commit_group;" ::: "memory")
#define CP_WAIT(n)  asm volatile("cp.async.wait_group %0;" :: "n"(n) : "memory")
#define LDSM4(r0, r1, r2, r3, a) \
    asm volatile("ldmatrix.sync.aligned.m8n8.x4.shared.b16 {%0,%1,%2,%3}, [%4];" \
        : "=r"(r0), "=r"(r1), "=r"(r2), "=r"(r3) : "r"(a))
__device__ __forceinline__ void mma16816(float c[4], unsigned a0, unsigned a1, unsigned a2, unsigned a3,
                                         unsigned b0, unsigned b1) {
    asm volatile("mma.sync.aligned.m16n8k16.row.col.f32.bf16.bf16.f32 "
        "{%0,%1,%2,%3}, {%4,%5,%6,%7}, {%8,%9}, {%0,%1,%2,%3};"
        : "+f"(c[0]), "+f"(c[1]), "+f"(c[2]), "+f"(c[3])
        : "r"(a0), "r"(a1), "r"(a2), "r"(a3), "r"(b0), "r"(b1));
}
__device__ __forceinline__ unsigned pack2(float a, float b) {
    __nv_bfloat162 t = __floats2bfloat162_rn(a, b);
    return *(unsigned*)&t;
}

// ---------------- smem layout (bytes): M=64 GEMM CTAs, 2 CTA/SM ----------------
#define OFF_ALO_B 33792
#define OFF_W_B   67584
#define OFF_BAR_B 100352
#define TSMEM     100416

// ---------------- setup kernels ----------------
__global__ void zero4(float4* __restrict__ dst, int n4) {
    int i = blockIdx.x * 256 + threadIdx.x;
    if (i < n4) dst[i] = make_float4(0.f, 0.f, 0.f, 0.f);
}
__global__ void split_init(const float* __restrict__ nodes) {
    size_t i2 = (size_t)blockIdx.x * 256 + threadIdx.x;
    float2 v = ((const float2*)nodes)[i2];
    ((float2*)g_h)[i2] = v;
    float h0 = __bfloat162float(__float2bfloat16(v.x));
    float h1 = __bfloat162float(__float2bfloat16(v.y));
    g_hhi[i2] = pack2(h0, h1);
    g_hlo[i2] = pack2(v.x - h0, v.y - h1);
}
__global__ void prep_weights(const float* __restrict__ w1, const float* __restrict__ w2,
                             const float* __restrict__ wih, const float* __restrict__ whh) {
    int idx = blockIdx.x * 256 + threadIdx.x;
    if (idx < 2 * SS * 256 * 256) {
        int k  = idx & 255;
        int n  = (idx >> 8) & 255;
        int si = (idx >> 16) & 1;
        int st = idx >> 17;
        float w = (st == 0 ? w1 : w2)[si * 65536 + n * 256 + k];
        __nv_bfloat16 hi = __float2bfloat16(w);
        __nv_bfloat16 lo = __float2bfloat16(w - __bfloat162float(hi));
        int ch = k >> 4;
        int word = n * 8 + (((((k >> 3) & 1)) ^ ((n >> 2) & 1)) << 2) + ((k & 7) >> 1);
        ((__nv_bfloat16*)&g_ewt[st][si][ch][0][word])[k & 1] = hi;
        ((__nv_bfloat16*)&g_ewt[st][si][ch][1][word])[k & 1] = lo;
    }
    if (idx < 2 * 768 * 256) {
        int k = idx & 255;
        int e = (idx >> 8) % 768;
        int wh = idx / (768 * 256);
        float w = (wh == 0 ? wih : whh)[e * 256 + k];
        __nv_bfloat16 hi = __float2bfloat16(w);
        __nv_bfloat16 lo = __float2bfloat16(w - __bfloat162float(hi));
        int ny = e >> 8, n = e & 255;
        int ch = k >> 4;
        int word = n * 8 + (((((k >> 3) & 1)) ^ ((n >> 2) & 1)) << 2) + ((k & 7) >> 1);
        ((__nv_bfloat16*)&g_gwt[wh][ny][ch][0][word])[k & 1] = hi;
        ((__nv_bfloat16*)&g_gwt[wh][ny][ch][1][word])[k & 1] = lo;
    }
}
__global__ void deg_count(const int* __restrict__ edges) {
    int e = blockIdx.x * 256 + threadIdx.x;
    int b = blockIdx.y, si = blockIdx.z;
    int dst = ((const int2*)edges)[((size_t)(b * SS + si)) * EE + e].x;
    atomicAdd(&g_deg[si][b * NN + dst], 1.0f);
}
__global__ void scan_deg() {
    int si = blockIdx.x, t = threadIdx.x;
    __shared__ int ps[1024];
    int base = t * 40;
    int s = 0;
    for (int i = 0; i < 40; ++i) {
        int idx = base + i;
        if (idx < MROWS) s += (int)g_deg[si][idx];
    }
    ps[t] = s;
    __syncthreads();
    for (int off = 1; off < 1024; off <<= 1) {
        int v = (t >= off) ? ps[t - off] : 0;
        __syncthreads();
        ps[t] += v;
        __syncthreads();
    }
    int run = ps[t] - s;
    for (int i = 0; i < 40; ++i) {
        int idx = base + i;
        if (idx < MROWS) {
            g_off[si][idx] = run;
            g_cur[si][idx] = run;
            run += (int)g_deg[si][idx];
        }
    }
}
__global__ void csr_fill(const int* __restrict__ edges) {
    int e = blockIdx.x * 256 + threadIdx.x;
    int b = blockIdx.y, si = blockIdx.z;
    int2 de = ((const int2*)edges)[((size_t)(b * SS + si)) * EE + e];
    int pos = atomicAdd(&g_cur[si][b * NN + de.x], 1);
    g_csr[si][pos] = b * NN + de.y;
}

// ---------------- HMMA for one 16-k chunk ----------------
__device__ __forceinline__ void hmma_chunk16(
    unsigned aHi, unsigned aLo, unsigned wB, float acc[2][8][4])
{
    unsigned ah[2][4], al[2][4];
#pragma unroll
    for (int mt = 0; mt < 2; ++mt) {
        unsigned off = mt * (16 * AW_PITCH * 4);
        LDSM4(ah[mt][0], ah[mt][1], ah[mt][2], ah[mt][3], aHi + off);
        LDSM4(al[mt][0], al[mt][1], al[mt][2], al[mt][3], aLo + off);
    }
#pragma unroll
    for (int p = 0; p < 4; ++p) {
        unsigned bh[4], bl[4];
        LDSM4(bh[0], bh[1], bh[2], bh[3], wB + p * 512);
        LDSM4(bl[0], bl[1], bl[2], bl[3], wB + p * 512 + 8192);
#pragma unroll
        for (int mt = 0; mt < 2; ++mt) {
            mma16816(acc[mt][2*p],   ah[mt][0], ah[mt][1], ah[mt][2], ah[mt][3], bh[0], bh[1]);
            mma16816(acc[mt][2*p],   al[mt][0], al[mt][1], al[mt][2], al[mt][3], bh[0], bh[1]);
            mma16816(acc[mt][2*p],   ah[mt][0], ah[mt][1], ah[mt][2], ah[mt][3], bl[0], bl[1]);
            mma16816(acc[mt][2*p+1], ah[mt][0], ah[mt][1], ah[mt][2], ah[mt][3], bh[2], bh[3]);
            mma16816(acc[mt][2*p+1], al[mt][0], al[mt][1], al[mt][2], al[mt][3], bh[2], bh[3]);
            mma16816(acc[mt][2*p+1], ah[mt][0], ah[mt][1], ah[mt][2], ah[mt][3], bl[2], bl[3]);
        }
    }
}
__device__ __forceinline__ unsigned b_thread_off(int wn, int lane) {
    return ((unsigned)(wn * 512 + ((lane >> 4) & 1) * 64 + (lane & 7) * 8) << 2)
         + ((((lane >> 3) ^ (lane >> 2)) & 1) << 4);
}
__device__ __forceinline__ void load_split_rows(
    unsigned* Ahw, unsigned* Alw, const float* __restrict__ src, int tid)
{
    int r = tid >> 2, q = tid & 3;
    const float4* sp = (const float4*)(src + (size_t)r * DD) + q * 16;
    unsigned* dh = Ahw + r * AW_PITCH + q * 32;
    unsigned* dl = Alw + r * AW_PITCH + q * 32;
#pragma unroll
    for (int i = 0; i < 16; ++i) {
        float4 v = sp[i];
        float h0 = __bfloat162float(__float2bfloat16(v.x));
        float h1 = __bfloat162float(__float2bfloat16(v.y));
        float h2 = __bfloat162float(__float2bfloat16(v.z));
        float h3 = __bfloat162float(__float2bfloat16(v.w));
        dh[2 * i]     = pack2(h0, h1);
        dh[2 * i + 1] = pack2(h2, h3);
        dl[2 * i]     = pack2(v.x - h0, v.y - h1);
        dl[2 * i + 1] = pack2(v.z - h2, v.w - h3);
    }
}
__device__ __forceinline__ void cp_split_rows(
    unsigned sb, const unsigned* __restrict__ hi, const unsigned* __restrict__ lo,
    size_t grow, int tid)
{
    int r = tid >> 2, q = tid & 3;
    unsigned dh = sb + (r * AW_PITCH + q * 32) * 4;
    unsigned dl = dh + OFF_ALO_B;
#pragma unroll
    for (int i = 0; i < 8; ++i) {
        CP16(dh + 16 * i, hi + grow + (size_t)r * 128 + q * 32 + 4 * i);
        CP16(dl + 16 * i, lo + grow + (size_t)r * 128 + q * 32 + 4 * i);
    }
    CP_COMMIT();
}

// ---------------- U GEMM: U_si = leaky(h * W1_si^T + b1_si) ----------------
__global__ void __launch_bounds__(256, 2) u_tc(const float* __restrict__ eb1) {
    extern __shared__ char smem[];
    unsigned sb = smem_u32(smem);
    unsigned bar = sb + OFF_BAR_B;
    int tid = threadIdx.x, lane = tid & 31, wid = tid >> 5;
    int wm = wid >> 2, wn = wid & 3;
    int row0 = blockIdx.x * 64, si = blockIdx.y;

    unsigned aHi0 = sb + (wm * 32 + (lane & 15)) * (AW_PITCH * 4) + (lane >> 4) * 16;
    unsigned wOff = b_thread_off(wn, lane);

    if (tid == 0) {
        MB_INIT(bar + 0, 1);  MB_INIT(bar + 8, 1);
        MB_INIT(bar + 16, 8); MB_INIT(bar + 24, 8);
    }
    __syncthreads();
    if (tid == 0) {
#pragma unroll
        for (int g = 0; g < 2; ++g) {
            MB_EXPECT(bar + 8 * g, 16384);
            bulk_g2s(sb + OFF_W_B + g * 16384, &g_ewt[0][si][g][0][0], 16384, bar + 8 * g);
        }
    }
    cp_split_rows(sb, g_hhi, g_hlo, (size_t)row0 * 128, tid);
    CP_WAIT(0);
    __syncthreads();

    float acc[2][8][4];
#pragma unroll
    for (int mt = 0; mt < 2; ++mt)
#pragma unroll
        for (int ng = 0; ng < 8; ++ng)
#pragma unroll
            for (int i = 0; i < 4; ++i) acc[mt][ng][i] = 0.f;

    int fph[2] = {0, 0}, eph[2] = {0, 0};
    for (int kc = 0; kc < 16; ++kc) {
        int buf = kc & 1;
        MB_WAIT(bar + 8 * buf, fph[buf]); fph[buf] ^= 1;
        hmma_chunk16(aHi0 + kc * 32, aHi0 + kc * 32 + OFF_ALO_B,
                     sb + OFF_W_B + buf * 16384 + wOff, acc);
        if (lane == 0) MB_ARRIVE(bar + 16 + 8 * buf);
        if (tid == 0 && kc < 14) {
            MB_WAIT(bar + 16 + 8 * buf, eph[buf]); eph[buf] ^= 1;
            MB_EXPECT(bar + 8 * buf, 16384);
            bulk_g2s(sb + OFF_W_B + buf * 16384, &g_ewt[0][si][kc + 2][0][0], 16384, bar + 8 * buf);
        }
    }

    const float* b1s = eb1 + si * DD;
    float* up = g_u[si];
#pragma unroll
    for (int mt = 0; mt < 2; ++mt) {
#pragma unroll
        for (int half = 0; half < 2; ++half) {
            int row = row0 + wm * 32 + mt * 16 + (lane >> 2) + half * 8;
            float* cp = up + (size_t)row * DD;
#pragma unroll
            for (int nf = 0; nf < 8; ++nf) {
                int ncol = wn * 64 + nf * 8 + (lane & 3) * 2;
                float2 bv = *(const float2*)(b1s + ncol);
                float v0 = acc[mt][nf][half * 2 + 0] + bv.x;
                float v1 = acc[mt][nf][half * 2 + 1] + bv.y;
                v0 = v0 > 0.f ? v0 : 0.01f * v0;
                v1 = v1 > 0.f ? v1 : 0.01f * v1;
                *(float2*)(cp + ncol) = make_float2(v0, v1);
            }
        }
    }
}

// ---------------- gather-sum (unrolled x2): T_si[row] = sum U_si[src] ----------
__global__ void __launch_bounds__(256) gather_sum() {
    int lane = threadIdx.x & 31;
    int w = blockIdx.x * 8 + (threadIdx.x >> 5);
    int si = w / MROWS, row = w - si * MROWS;
    int beg = g_off[si][row];
    int cnt = (int)g_deg[si][row];
    const float* ub = g_u[si];
    const int* cs = g_csr[si] + beg;
    float4 a0 = make_float4(0.f, 0.f, 0.f, 0.f);
    float4 a1 = make_float4(0.f, 0.f, 0.f, 0.f);
    int i = 0;
    for (; i + 2 <= cnt; i += 2) {
        const float4* p0 = (const float4*)(ub + (size_t)cs[i] * DD);
        const float4* p1 = (const float4*)(ub + (size_t)cs[i + 1] * DD);
        float4 u0 = p0[lane], u1 = p0[lane + 32];
        float4 v0 = p1[lane], v1 = p1[lane + 32];
        a0.x += u0.x + v0.x; a0.y += u0.y + v0.y; a0.z += u0.z + v0.z; a0.w += u0.w + v0.w;
        a1.x += u1.x + v1.x; a1.y += u1.y + v1.y; a1.z += u1.z + v1.z; a1.w += u1.w + v1.w;
    }
    if (i < cnt) {
        const float4* p0 = (const float4*)(ub + (size_t)cs[i] * DD);
        float4 u0 = p0[lane], u1 = p0[lane + 32];
        a0.x += u0.x; a0.y += u0.y; a0.z += u0.z; a0.w += u0.w;
        a1.x += u1.x; a1.y += u1.y; a1.z += u1.z; a1.w += u1.w;
    }
    size_t rb = (size_t)row * 128;
    unsigned* th = g_Thi[si];
    unsigned* tl = g_Tlo[si];
    float h0, h1;
    h0 = __bfloat162float(__float2bfloat16(a0.x)); h1 = __bfloat162float(__float2bfloat16(a0.y));
    th[rb + lane * 2 + 0] = pack2(h0, h1);
    tl[rb + lane * 2 + 0] = pack2(a0.x - h0, a0.y - h1);
    h0 = __bfloat162float(__float2bfloat16(a0.z)); h1 = __bfloat162float(__float2bfloat16(a0.w));
    th[rb + lane * 2 + 1] = pack2(h0, h1);
    tl[rb + lane * 2 + 1] = pack2(a0.z - h0, a0.w - h1);
    h0 = __bfloat162float(__float2bfloat16(a1.x)); h1 = __bfloat162float(__float2bfloat16(a1.y));
    th[rb + 64 + lane * 2 + 0] = pack2(h0, h1);
    tl[rb + 64 + lane * 2 + 0] = pack2(a1.x - h0, a1.y - h1);
    h0 = __bfloat162float(__float2bfloat16(a1.z)); h1 = __bfloat162float(__float2bfloat16(a1.w));
    th[rb + 64 + lane * 2 + 1] = pack2(h0, h1);
    tl[rb + 64 + lane * 2 + 1] = pack2(a1.z - h0, a1.w - h1);
}

// ---------------- inc GEMM: inc = T0*W2_0^T + T1*W2_1^T + deg*b2 terms ----------
__global__ void __launch_bounds__(256, 2) inc_tc(const float* __restrict__ eb2) {
    extern __shared__ char smem[];
    unsigned sb = smem_u32(smem);
    unsigned bar = sb + OFF_BAR_B;
    int tid = threadIdx.x, lane = tid & 31, wid = tid >> 5;
    int wm = wid >> 2, wn = wid & 3;
    int row0 = blockIdx.x * 64;

    unsigned aHi0 = sb + (wm * 32 + (lane & 15)) * (AW_PITCH * 4) + (lane >> 4) * 16;
    unsigned wOff = b_thread_off(wn, lane);

    if (tid == 0) {
        MB_INIT(bar + 0, 1);  MB_INIT(bar + 8, 1);
        MB_INIT(bar + 16, 8); MB_INIT(bar + 24, 8);
    }
    __syncthreads();
    if (tid == 0) {
#pragma unroll
        for (int g = 0; g < 2; ++g) {
            MB_EXPECT(bar + 8 * g, 16384);
            bulk_g2s(sb + OFF_W_B + g * 16384, &g_ewt[1][0][g][0][0], 16384, bar + 8 * g);
        }
    }
    cp_split_rows(sb, g_Thi[0], g_Tlo[0], (size_t)row0 * 128, tid);
    CP_WAIT(0);
    __syncthreads();

    float acc[2][8][4];
#pragma unroll
    for (int mt = 0; mt < 2; ++mt)
#pragma unroll
        for (int ng = 0; ng < 8; ++ng)
#pragma unroll
            for (int i = 0; i < 4; ++i) acc[mt][ng][i] = 0.f;

    int fph[2] = {0, 0}, eph[2] = {0, 0};
    for (int kc = 0; kc < 32; ++kc) {
        int buf = kc & 1;
        MB_WAIT(bar + 8 * buf, fph[buf]); fph[buf] ^= 1;
        if (kc == 16) {
            __syncthreads();
            cp_split_rows(sb, g_Thi[1], g_Tlo[1], (size_t)row0 * 128, tid);
            CP_WAIT(0);
            __syncthreads();
        }
        hmma_chunk16(aHi0 + (kc & 15) * 32, aHi0 + (kc & 15) * 32 + OFF_ALO_B,
                     sb + OFF_W_B + buf * 16384 + wOff, acc);
        if (lane == 0) MB_ARRIVE(bar + 16 + 8 * buf);
        if (tid == 0 && kc < 30) {
            MB_WAIT(bar + 16 + 8 * buf, eph[buf]); eph[buf] ^= 1;
            int c1 = kc + 2, si2 = c1 >> 4, ch = c1 & 15;
            MB_EXPECT(bar + 8 * buf, 16384);
            bulk_g2s(sb + OFF_W_B + buf * 16384, &g_ewt[1][si2][ch][0][0], 16384, bar + 8 * buf);
        }
    }

    const float* b20 = eb2;
    const float* b21 = eb2 + DD;
#pragma unroll
    for (int mt = 0; mt < 2; ++mt) {
#pragma unroll
        for (int half = 0; half < 2; ++half) {
            int row = row0 + wm * 32 + mt * 16 + (lane >> 2) + half * 8;
            float d0 = g_deg[0][row];
            float d1 = g_deg[1][row];
            float* cp = g_inc + (size_t)row * DD;
#pragma unroll
            for (int nf = 0; nf < 8; ++nf) {
                int ncol = wn * 64 + nf * 8 + (lane & 3) * 2;
                float2 p0 = *(const float2*)(b20 + ncol);
                float2 p1 = *(const float2*)(b21 + ncol);
                float2 v;
                v.x = acc[mt][nf][half * 2 + 0] + d0 * p0.x + d1 * p1.x;
                v.y = acc[mt][nf][half * 2 + 1] + d0 * p0.y + d1 * p1.y;
                *(float2*)(cp + ncol) = v;
            }
        }
    }
}

// ---------------- GRU GEMM: merged launch, which = blockIdx.z ----------------
__global__ void __launch_bounds__(256, 2) gru_tc(
    const float* __restrict__ b_ih, const float* __restrict__ b_hh)
{
    extern __shared__ char smem[];
    unsigned sb = smem_u32(smem);
    unsigned* Ahw = (unsigned*)smem;
    unsigned* Alw = Ahw + OFF_ALO_B / 4;
    unsigned bar = sb + OFF_BAR_B;

    int tid = threadIdx.x, lane = tid & 31, wid = tid >> 5;
    int wm = wid >> 2, wn = wid & 3;
    int row0 = blockIdx.x * 64;
    int ny = blockIdx.y, col0 = ny * 256;
    int which = blockIdx.z;

    unsigned aHi0 = sb + (wm * 32 + (lane & 15)) * (AW_PITCH * 4) + (lane >> 4) * 16;
    unsigned wOff = b_thread_off(wn, lane);

    if (tid == 0) {
        MB_INIT(bar + 0, 1);  MB_INIT(bar + 8, 1);
        MB_INIT(bar + 16, 8); MB_INIT(bar + 24, 8);
    }
    __syncthreads();
    if (tid == 0) {
#pragma unroll
        for (int g = 0; g < 2; ++g) {
            MB_EXPECT(bar + 8 * g, 16384);
            bulk_g2s(sb + OFF_W_B + g * 16384, &g_gwt[which][ny][g][0][0], 16384, bar + 8 * g);
        }
    }
    if (which == 1) {
        cp_split_rows(sb, g_hhi, g_hlo, (size_t)row0 * 128, tid);
        CP_WAIT(0);
    } else {
        load_split_rows(Ahw, Alw, g_inc + (size_t)row0 * DD, tid);
    }
    __syncthreads();

    float acc[2][8][4];
#pragma unroll
    for (int mt = 0; mt < 2; ++mt)
#pragma unroll
        for (int ng = 0; ng < 8; ++ng)
#pragma unroll
            for (int i = 0; i < 4; ++i) acc[mt][ng][i] = 0.f;

    int fph[2] = {0, 0}, eph[2] = {0, 0};
    for (int kc = 0; kc < 16; ++kc) {
        int buf = kc & 1;
        MB_WAIT(bar + 8 * buf, fph[buf]); fph[buf] ^= 1;
        hmma_chunk16(aHi0 + kc * 32, aHi0 + kc * 32 + OFF_ALO_B,
                     sb + OFF_W_B + buf * 16384 + wOff, acc);
        if (lane == 0) MB_ARRIVE(bar + 16 + 8 * buf);
        if (tid == 0 && kc < 14) {
            MB_WAIT(bar + 16 + 8 * buf, eph[buf]); eph[buf] ^= 1;
            MB_EXPECT(bar + 8 * buf, 16384);
            bulk_g2s(sb + OFF_W_B + buf * 16384, &g_gwt[which][ny][kc + 2][0][0], 16384, bar + 8 * buf);
        }
    }

    const float* bias = (which == 0 ? b_ih : b_hh);
    float* C = (which == 0 ? g_gi : g_gh);
#pragma unroll
    for (int mt = 0; mt < 2; ++mt) {
#pragma unroll
        for (int half = 0; half < 2; ++half) {
            int row = row0 + wm * 32 + mt * 16 + (lane >> 2) + half * 8;
            float* cp = C + (size_t)row * 768 + col0;
#pragma unroll
            for (int nf = 0; nf < 8; ++nf) {
                int ncol = wn * 64 + nf * 8 + (lane & 3) * 2;
                float2 bv = *(const float2*)(bias + col0 + ncol);
                float2 v;
                v.x = acc[mt][nf][half * 2 + 0] + bv.x;
                v.y = acc[mt][nf][half * 2 + 1] + bv.y;
                *(float2*)(cp + ncol) = v;
            }
        }
    }
}

// ---------------- GRU gates + h split refresh ----------------
__global__ void gru_gate2(const float* __restrict__ gi, const float* __restrict__ gh) {
    size_t i2 = (size_t)blockIdx.x * 256 + threadIdx.x;
    size_t row = i2 >> 7;
    int d = (int)(i2 & 127) * 2;
    const float* gir = gi + row * 768;
    const float* ghr = gh + row * 768;
    float2 ir = *(const float2*)(gir + d);
    float2 iz = *(const float2*)(gir + 256 + d);
    float2 in2 = *(const float2*)(gir + 512 + d);
    float2 hr = *(const float2*)(ghr + d);
    float2 hz = *(const float2*)(ghr + 256 + d);
    float2 hn = *(const float2*)(ghr + 512 + d);
    float2 hv = ((const float2*)g_h)[i2];
    float r0 = 1.f / (1.f + expf(-(ir.x + hr.x)));
    float r1 = 1.f / (1.f + expf(-(ir.y + hr.y)));
    float z0 = 1.f / (1.f + expf(-(iz.x + hz.x)));
    float z1 = 1.f / (1.f + expf(-(iz.y + hz.y)));
    float n0 = tanhf(in2.x + r0 * hn.x);
    float n1 = tanhf(in2.y + r1 * hn.y);
    float h0 = (1.f - z0) * n0 + z0 * hv.x;
    float h1 = (1.f - z1) * n1 + z1 * hv.y;
    ((float2*)g_h)[i2] = make_float2(h0, h1);
    float e0 = __bfloat162float(__float2bfloat16(h0));
    float e1 = __bfloat162float(__float2bfloat16(h1));
    g_hhi[i2] = pack2(e0, e1);
    g_hlo[i2] = pack2(h0 - e0, h1 - e1);
}

// ---------------- node sum + head ----------------
__global__ void node_sum() {
    int b = blockIdx.x, chunk = blockIdx.y;
    int d = threadIdx.x;
    const float* base = g_h + ((size_t)b * NN + chunk * 250) * DD + d;
    float acc = 0.f;
    for (int n = 0; n < 250; ++n) acc += base[(size_t)n * DD];
    atomicAdd(&g_s[b * DD + d], acc);
}

__global__ void head_kernel(const float* __restrict__ ptype,
                            const float* __restrict__ fc1w, const float* __restrict__ fc1b,
                            const float* __restrict__ fc2w, const float* __restrict__ fc2b,
                            const float* __restrict__ fc3w, const float* __restrict__ fc3b,
                            float* __restrict__ out)
{
    int b = blockIdx.x, tid = threadIdx.x;
    __shared__ float xs[257];
    __shared__ float red[256];
    __shared__ float a1[HID], a2[HID];

    float sv = g_s[b * DD + tid];
    float l = logf(sv);
    if (isnan(l)) l = 0.f;
    l = fmaxf(l, 0.f);
    float fm = isinf(l) ? -INFINITY : l;
    red[tid] = fm;
    __syncthreads();
    for (int off = 128; off > 0; off >>= 1) {
        if (tid < off) red[tid] = fmaxf(red[tid], red[tid + off]);
        __syncthreads();
    }
    float fmax = red[0];
    if (isinf(l)) l = fmax;
    xs[tid] = l;
    if (tid == 0) xs[256] = ptype[b];
    __syncthreads();

    if (tid < HID) {
        float acc = fc1b[tid];
        for (int k = 0; k < 257; ++k) acc += fc1w[tid * 257 + k] * xs[k];
        a1[tid] = acc > 0.f ? acc : 0.01f * acc;
    }
    __syncthreads();
    if (tid < HID) {
        float acc = fc2b[tid];
        for (int k = 0; k < HID; ++k) acc += fc2w[tid * HID + k] * a1[k];
        a2[tid] = acc > 0.f ? acc : 0.01f * acc;
    }
    __syncthreads();
    if (tid < OUTD) {
        float acc = fc3b[tid];
        for (int k = 0; k < HID; ++k) acc += fc3w[tid * HID + k] * a2[k];
        out[b * OUTD + tid] = acc;
    }
}

// ---------------- launch ----------------
extern "C" void kernel_launch(void* const* d_in, const int* in_sizes, int n_in,
                              void* d_out, int out_size) {
    const float* nodes = (const float*)d_in[0];
    const int*   edges = (const int*)  d_in[1];
    const float* ptype = (const float*)d_in[2];
    const float* w_ih  = (const float*)d_in[3];
    const float* w_hh  = (const float*)d_in[4];
    const float* b_ih  = (const float*)d_in[5];
    const float* b_hh  = (const float*)d_in[6];
    const float* ew1   = (const float*)d_in[7];
    const float* eb1   = (const float*)d_in[8];
    const float* ew2   = (const float*)d_in[9];
    const float* eb2   = (const float*)d_in[10];
    const float* fc1w  = (const float*)d_in[11];
    const float* fc1b  = (const float*)d_in[12];
    const float* fc2w  = (const float*)d_in[13];
    const float* fc2b  = (const float*)d_in[14];
    const float* fc3w  = (const float*)d_in[15];
    const float* fc3b  = (const float*)d_in[16];
    float* out = (float*)d_out;

    float *p_gi, *p_gh, *p_s, *p_deg;
    cudaGetSymbolAddress((void**)&p_gi,  g_gi);
    cudaGetSymbolAddress((void**)&p_gh,  g_gh);
    cudaGetSymbolAddress((void**)&p_s,   g_s);
    cudaGetSymbolAddress((void**)&p_deg, g_deg);

    cudaFuncSetAttribute(u_tc,   cudaFuncAttributeMaxDynamicSharedMemorySize, TSMEM);
    cudaFuncSetAttribute(inc_tc, cudaFuncAttributeMaxDynamicSharedMemorySize, TSMEM);
    cudaFuncSetAttribute(gru_tc, cudaFuncAttributeMaxDynamicSharedMemorySize, TSMEM);

    const int GRID_R = MROWS / 64;           // 625

    split_init<<<MROWS * 128 / 256, 256>>>(nodes);
    prep_weights<<<1536, 256>>>(ew1, ew2, w_ih, w_hh);
    zero4<<<(SS * MROWS / 4 + 255) / 256, 256>>>((float4*)p_deg, SS * MROWS / 4);
    deg_count<<<dim3(EE / 256, BB, SS), 256>>>(edges);
    scan_deg<<<SS, 1024>>>();
    csr_fill<<<dim3(EE / 256, BB, SS), 256>>>(edges);

    for (int j = 0; j < NPASS; ++j) {
        u_tc<<<dim3(GRID_R, SS), 256, TSMEM>>>(eb1);
        gather_sum<<<SS * MROWS / 8, 256>>>();
        inc_tc<<<GRID_R, 256, TSMEM>>>(eb2);
        gru_tc<<<dim3(GRID_R, 3, 2), 256, TSMEM>>>(b_ih, b_hh);
        gru_gate2<<<MROWS * 128 / 256, 256>>>(p_gi, p_gh);
    }

    zero4<<<1, 256>>>((float4*)p_s, BB * DD / 4);
    node_sum<<<dim3(BB, 40), 256>>>();
    head_kernel<<<BB, 256>>>(ptype, fc1w, fc1b, fc2w, fc2b, fc3w, fc3b, out);
}